// round 4
// baseline (speedup 1.0000x reference)
#include <cuda_runtime.h>

#define POOL 7
#define NROI 32
#define NB   8
#define NC   1024
#define IMG_W 64
#define IMG_H 64
#define PP   (POOL * POOL)

struct Quad { float4 a, b, c, d; };

__device__ __forceinline__ void load_quad(Quad& q,
                                          const float* __restrict__ row0,
                                          const float* __restrict__ row1,
                                          int X0, int X1, int t) {
    const float4* p00 = (const float4*)(row0 + (size_t)X0 * NC);
    const float4* p01 = (const float4*)(row0 + (size_t)X1 * NC);
    const float4* p10 = (const float4*)(row1 + (size_t)X0 * NC);
    const float4* p11 = (const float4*)(row1 + (size_t)X1 * NC);
    q.a = __ldg(p00 + t);
    q.b = __ldg(p01 + t);
    q.c = __ldg(p10 + t);
    q.d = __ldg(p11 + t);
}

__device__ __forceinline__ void edge_x(int px, int rx, int rw, int& X0, int& X1, float& wx) {
    float cx = ((float)px + 0.5f) * ((float)rw / (float)POOL) - 0.5f;
    float fx = floorf(cx);
    int lox = max((int)fx, 0);
    int hix = min(max((int)ceilf(cx), 0), rw - 1);
    wx = cx - fx;
    X0 = rx + lox;
    X1 = rx + hix;
}

__device__ __forceinline__ float4 blerp(const Quad& q, float wx, float wy) {
    float4 o;
    float t0, b0;
    t0 = q.a.x + (q.b.x - q.a.x) * wx;
    b0 = q.c.x + (q.d.x - q.c.x) * wx;
    o.x = t0 + (b0 - t0) * wy;
    t0 = q.a.y + (q.b.y - q.a.y) * wx;
    b0 = q.c.y + (q.d.y - q.c.y) * wx;
    o.y = t0 + (b0 - t0) * wy;
    t0 = q.a.z + (q.b.z - q.a.z) * wx;
    b0 = q.c.z + (q.d.z - q.c.z) * wx;
    o.z = t0 + (b0 - t0) * wy;
    t0 = q.a.w + (q.b.w - q.a.w) * wx;
    b0 = q.c.w + (q.d.w - q.c.w) * wx;
    o.w = t0 + (b0 - t0) * wy;
    return o;
}

// One block per (b, r, py) row: 7 px positions, double-buffered loads.
__global__ __launch_bounds__(256, 4)
void roi_row_kernel(const float* __restrict__ img,
                    const int*   __restrict__ rois,
                    float*       __restrict__ out) {
    // Batch-major ordering for L2 locality: blk = (b*NROI + r)*POOL + py
    int blk = blockIdx.x;
    int b   = blk / (NROI * POOL);
    int rem = blk - b * (NROI * POOL);
    int r   = rem / POOL;
    int py  = rem - r * POOL;

    const int4 roi = __ldg((const int4*)rois + r);  // x, y, w, h

    // Vertical edge (fixed for the whole row-block)
    float cy = ((float)py + 0.5f) * ((float)roi.w / (float)POOL) - 0.5f;
    float fy = floorf(cy);
    int loy = max((int)fy, 0);
    int hiy = min(max((int)ceilf(cy), 0), roi.w - 1);
    float wy = cy - fy;
    int Y0 = roi.y + loy;
    int Y1 = roi.y + hiy;

    const float* row0 = img + ((size_t)b * (IMG_H * IMG_W) + (size_t)Y0 * IMG_W) * NC;
    const float* row1 = img + ((size_t)b * (IMG_H * IMG_W) + (size_t)Y1 * IMG_W) * NC;

    // Output: (r, b, py, px, c) flattened
    float4* po = (float4*)(out + ((((size_t)r * NB + b) * POOL + py) * POOL) * NC);

    int t = threadIdx.x;  // channel group of 4 floats

    // Prefetch px = 0
    int X0, X1; float wx;
    edge_x(0, roi.x, roi.z, X0, X1, wx);
    Quad cur;
    load_quad(cur, row0, row1, X0, X1, t);
    float wx_cur = wx;

    #pragma unroll
    for (int px = 0; px < POOL; px++) {
        Quad nxt;
        float wx_nxt = 0.f;
        if (px + 1 < POOL) {
            int nX0, nX1;
            edge_x(px + 1, roi.x, roi.z, nX0, nX1, wx_nxt);
            load_quad(nxt, row0, row1, nX0, nX1, t);
        }
        float4 o = blerp(cur, wx_cur, wy);
        __stcs(po + (size_t)px * (NC / 4) + t, o);
        cur = nxt;
        wx_cur = wx_nxt;
    }
}

extern "C" void kernel_launch(void* const* d_in, const int* in_sizes, int n_in,
                              void* d_out, int out_size) {
    const float* img  = (const float*)d_in[0];
    const int*   rois = (const int*)d_in[1];
    if (n_in >= 2 && in_sizes[0] == NROI * 4) {
        img  = (const float*)d_in[1];
        rois = (const int*)d_in[0];
    }
    float* out = (float*)d_out;

    dim3 grid(NB * NROI * POOL);  // 1792
    dim3 block(256);
    roi_row_kernel<<<grid, block>>>(img, rois, out);
}